// round 7
// baseline (speedup 1.0000x reference)
#include <cuda_runtime.h>
#include <cuda_fp16.h>
#include <math.h>
#include <stdint.h>

#define EMBED 1024
#define HEADS 16
#define HDIM  64
#define BATCH 2
#define SEQ   2048
#define M_TOT (BATCH*SEQ)   // 4096

// ---------------- scratch (device globals; allocation-free) ----------------
__device__ __align__(16) __half g_xa[M_TOT*EMBED];   // query act / AO
__device__ __align__(16) __half g_xb[M_TOT*EMBED];   // key act
__device__ __align__(16) __half g_xc[M_TOT*EMBED];   // value act
__device__ __align__(16) __half g_w0[EMBED*EMBED];   // Wq
__device__ __align__(16) __half g_w1[EMBED*EMBED];   // Wk
__device__ __align__(16) __half g_w2[EMBED*EMBED];   // Wv
__device__ __align__(16) __half g_w3[EMBED*EMBED];   // Wo
__device__ __align__(16) __half g_q16[BATCH*HEADS*SEQ*HDIM];
__device__ __align__(16) __half g_k16[BATCH*HEADS*SEQ*HDIM];
__device__ __align__(16) __half g_v16[BATCH*HEADS*SEQ*HDIM];

// ---------------------------------------------------------------------------
// fp32 -> fp16, fused across tensors: blockIdx.y selects tensor.
// Each block converts 4096 floats.
// ---------------------------------------------------------------------------
__global__ __launch_bounds__(256) void cvt_acts(const float* __restrict__ a,
                                                const float* __restrict__ b,
                                                const float* __restrict__ c,
                                                __half* __restrict__ ha,
                                                __half* __restrict__ hb,
                                                __half* __restrict__ hc)
{
    const float* x = (blockIdx.y == 0) ? a : (blockIdx.y == 1) ? b : c;
    __half* h      = (blockIdx.y == 0) ? ha : (blockIdx.y == 1) ? hb : hc;
    const float4* src = (const float4*)x + (size_t)blockIdx.x * 1024;
    uint2* dst = (uint2*)h + (size_t)blockIdx.x * 1024;
    const int tid = threadIdx.x;
    #pragma unroll
    for (int j = 0; j < 4; j++) {
        float4 v = src[j * 256 + tid];
        __half2 p = __floats2half2_rn(v.x, v.y);
        __half2 q = __floats2half2_rn(v.z, v.w);
        uint2 r;
        r.x = reinterpret_cast<uint32_t&>(p);
        r.y = reinterpret_cast<uint32_t&>(q);
        dst[j * 256 + tid] = r;
    }
}

__global__ __launch_bounds__(256) void cvt_wts(const float* __restrict__ a,
                                               const float* __restrict__ b,
                                               const float* __restrict__ c,
                                               const float* __restrict__ d,
                                               __half* __restrict__ ha,
                                               __half* __restrict__ hb,
                                               __half* __restrict__ hc,
                                               __half* __restrict__ hd)
{
    const float* x = (blockIdx.y == 0) ? a : (blockIdx.y == 1) ? b
                   : (blockIdx.y == 2) ? c : d;
    __half* h      = (blockIdx.y == 0) ? ha : (blockIdx.y == 1) ? hb
                   : (blockIdx.y == 2) ? hc : hd;
    const float4* src = (const float4*)x + (size_t)blockIdx.x * 1024;
    uint2* dst = (uint2*)h + (size_t)blockIdx.x * 1024;
    const int tid = threadIdx.x;
    #pragma unroll
    for (int j = 0; j < 4; j++) {
        float4 v = src[j * 256 + tid];
        __half2 p = __floats2half2_rn(v.x, v.y);
        __half2 q = __floats2half2_rn(v.z, v.w);
        uint2 r;
        r.x = reinterpret_cast<uint32_t&>(p);
        r.y = reinterpret_cast<uint32_t&>(q);
        dst[j * 256 + tid] = r;
    }
}

// ---------------------------------------------------------------------------
// warp-MMA helpers
// ---------------------------------------------------------------------------
__device__ __forceinline__ uint32_t s2u(const void* p) {
    uint32_t a;
    asm("{ .reg .u64 t; cvta.to.shared.u64 t, %1; cvt.u32.u64 %0, t; }" : "=r"(a) : "l"(p));
    return a;
}

__device__ __forceinline__ void ldmx4(uint32_t& r0, uint32_t& r1, uint32_t& r2, uint32_t& r3,
                                      uint32_t addr)
{
    asm volatile("ldmatrix.sync.aligned.m8n8.x4.shared.b16 {%0,%1,%2,%3}, [%4];"
                 : "=r"(r0), "=r"(r1), "=r"(r2), "=r"(r3) : "r"(addr));
}

__device__ __forceinline__ void ldmx4t(uint32_t& r0, uint32_t& r1, uint32_t& r2, uint32_t& r3,
                                       uint32_t addr)
{
    asm volatile("ldmatrix.sync.aligned.m8n8.x4.trans.shared.b16 {%0,%1,%2,%3}, [%4];"
                 : "=r"(r0), "=r"(r1), "=r"(r2), "=r"(r3) : "r"(addr));
}

__device__ __forceinline__ void mma16816(float* d, const uint32_t* a, const uint32_t* b)
{
    asm volatile("mma.sync.aligned.m16n8k16.row.col.f32.f16.f16.f32 "
                 "{%0,%1,%2,%3}, {%4,%5,%6,%7}, {%8,%9}, {%0,%1,%2,%3};"
                 : "+f"(d[0]), "+f"(d[1]), "+f"(d[2]), "+f"(d[3])
                 : "r"(a[0]), "r"(a[1]), "r"(a[2]), "r"(a[3]), "r"(b[0]), "r"(b[1]));
}

__device__ __forceinline__ void cpasync16(uint32_t saddr, const void* gaddr)
{
    asm volatile("cp.async.cg.shared.global [%0], [%1], 16;" :: "r"(saddr), "l"(gaddr));
}

__device__ __forceinline__ uint32_t swz(uint32_t off) { return off ^ ((off >> 3) & 0x70); }

__device__ __forceinline__ uint32_t pack_h2(float x, float y) {
    __half2 t = __floats2half2_rn(x, y);
    return reinterpret_cast<uint32_t&>(t);
}

__device__ __forceinline__ uint32_t exp2_h2(float t0, float t1) {
    uint32_t r;
    asm("{ .reg .b32 t; cvt.rn.f16x2.f32 t, %2, %1; ex2.approx.f16x2 %0, t; }"
        : "=r"(r) : "f"(t0), "f"(t1));
    return r;
}

// ---------------------------------------------------------------------------
// Tensor-core GEMM (round-5 proven shape): C[m][n] = sum_k X[m][k]*W[n][k]
// CTA tile 128x128, BK=64, 8 warps (2m x 4n, warptile 64x32), 4-stage pipeline.
// blockIdx.z selects (X, W, out). SPLIT: fp16 (B,H,S,D); else fp32 (B,S,E).
// ---------------------------------------------------------------------------
#define GSTG  32768u                   // A 16K | B 16K
#define GSMEM (4 * GSTG)               // 128 KB

template<bool SPLIT>
__global__ __launch_bounds__(256, 1) void gemm_tc(
    const __half* __restrict__ xa, const __half* __restrict__ xb, const __half* __restrict__ xc,
    const __half* __restrict__ wa, const __half* __restrict__ wb, const __half* __restrict__ wc,
    float* __restrict__ out,
    __half* __restrict__ oa, __half* __restrict__ ob, __half* __restrict__ oc)
{
    const int z = blockIdx.z;
    const __half* x16 = (z == 0) ? xa : (z == 1) ? xb : xc;
    const __half* w16 = (z == 0) ? wa : (z == 1) ? wb : wc;
    __half* outh      = (z == 0) ? oa : (z == 1) ? ob : oc;

    extern __shared__ char smg[];
    const uint32_t sb = s2u(smg);
    const int tid  = threadIdx.x;
    const int wid  = tid >> 5, lane = tid & 31;
    const int wm   = wid & 1;
    const int wn   = wid >> 1;
    const int m0   = blockIdx.x * 128;
    const int n0   = blockIdx.y * 128;

    const int ldr = tid >> 3;
    const int ldc = tid & 7;

    auto issue = [&](int c, bool real) {
        if (real) {
            const uint32_t sst = sb + (uint32_t)(c & 3) * GSTG;
            const int kc0 = c * 64;
            const __half* gA = x16 + (size_t)m0 * EMBED + kc0;
            const __half* gB = w16 + (size_t)n0 * EMBED + kc0;
            #pragma unroll
            for (int it = 0; it < 4; it++) {
                const int r = ldr + it * 32;
                const uint32_t o = swz((uint32_t)(r * 128 + ldc * 16));
                const size_t g = (size_t)r * EMBED + ldc * 8;
                cpasync16(sst +          o, gA + g);
                cpasync16(sst + 16384u + o, gB + g);
            }
        }
        asm volatile("cp.async.commit_group;" ::: "memory");
    };

    float d[4][4][4];
    #pragma unroll
    for (int mi = 0; mi < 4; mi++)
        #pragma unroll
        for (int ni = 0; ni < 4; ni++)
            #pragma unroll
            for (int r = 0; r < 4; r++) d[mi][ni][r] = 0.f;

    issue(0, true); issue(1, true); issue(2, true); issue(3, true);

    const int arow = lane & 15;
    const int akc  = (lane & 16) >> 1;
    const int brow = (lane & 7) | ((lane & 16) >> 1);
    const int bkc  = lane & 8;

    const int NCHUNK = EMBED / 64;   // 16
    for (int c = 0; c < NCHUNK; c++) {
        asm volatile("cp.async.wait_group 3;" ::: "memory");
        __syncthreads();

        const uint32_t sst = sb + (uint32_t)(c & 3) * GSTG;
        const uint32_t bBase = sst + 16384u;

        #pragma unroll
        for (int ks = 0; ks < 4; ks++) {
            uint32_t a[4][4];
            #pragma unroll
            for (int mi = 0; mi < 4; mi++) {
                const int row = wm * 64 + mi * 16 + arow;
                const uint32_t off = swz((uint32_t)(row * 128 + (ks * 16 + akc) * 2));
                ldmx4(a[mi][0], a[mi][1], a[mi][2], a[mi][3], sst + off);
            }
            uint32_t b[4][2];
            #pragma unroll
            for (int bi = 0; bi < 2; bi++) {
                const int row = wn * 32 + bi * 16 + brow;
                const uint32_t off = swz((uint32_t)(row * 128 + (ks * 16 + bkc) * 2));
                uint32_t r0, r1, r2, r3;
                ldmx4(r0, r1, r2, r3, bBase + off);
                b[bi*2  ][0] = r0; b[bi*2  ][1] = r1;
                b[bi*2+1][0] = r2; b[bi*2+1][1] = r3;
            }
            #pragma unroll
            for (int mi = 0; mi < 4; mi++)
                #pragma unroll
                for (int ni = 0; ni < 4; ni++)
                    mma16816(d[mi][ni], a[mi], b[ni]);
        }
        __syncthreads();
        issue(c + 4, c + 4 < NCHUNK);
    }

    const int g4 = lane >> 2, t4 = lane & 3;
    #pragma unroll
    for (int mi = 0; mi < 4; mi++) {
        #pragma unroll
        for (int half = 0; half < 2; half++) {
            const int m = m0 + wm * 64 + mi * 16 + g4 + half * 8;
            const int bb = m >> 11, ssq = m & (SEQ - 1);
            #pragma unroll
            for (int ni = 0; ni < 4; ni++) {
                const int n = n0 + wn * 32 + ni * 8 + t4 * 2;
                const float vx = d[mi][ni][half * 2 + 0];
                const float vy = d[mi][ni][half * 2 + 1];
                if (SPLIT) {
                    const int h = n >> 6, dd = n & 63;
                    const size_t idx = (((size_t)(bb * HEADS + h)) * SEQ + ssq) * HDIM + dd;
                    *(uint32_t*)(outh + idx) = pack_h2(vx, vy);
                } else {
                    float2 v; v.x = vx; v.y = vy;
                    *(float2*)(out + (size_t)m * EMBED + n) = v;
                }
            }
        }
    }
}

// ---------------------------------------------------------------------------
// Flash attention on HMMA (round-6 version: f16x2 exp, l via ones-MMA,
// diagonal-tile work skipping). CTA: 128 q-rows; 8 warps; 4-stage KV pipeline.
// ---------------------------------------------------------------------------
#define FSTG  32768u
#define FSMEM (16384 + 4 * FSTG)
#define LOG2E 1.4426950408889634f

__global__ __launch_bounds__(256, 1) void flash_tc(
    const __half* __restrict__ q16, const __half* __restrict__ k16,
    const __half* __restrict__ v16, __half* __restrict__ oh)
{
    extern __shared__ char smf[];
    const uint32_t sb = s2u(smf);
    const int tid  = threadIdx.x;
    const int wid  = tid >> 5, lane = tid & 31;
    const int g4   = lane >> 2, t4 = lane & 3;
    const int bh   = blockIdx.y;
    const int b    = bh >> 4, head = bh & 15;
    const int qt   = (int)gridDim.x - 1 - (int)blockIdx.x;   // heavy tiles first
    const int q0   = qt * 128;

    const size_t bo = (size_t)bh * SEQ * HDIM;
    const __half* Qp = q16 + bo + (size_t)q0 * HDIM;
    const __half* Kp = k16 + bo;
    const __half* Vp = v16 + bo;

    const int ldr = tid >> 3, ldc = tid & 7;
    auto loadTile = [&](uint32_t dst, const __half* src) {
        #pragma unroll
        for (int it = 0; it < 4; it++) {
            const int r = ldr + it * 32;
            cpasync16(sb + dst + swz((uint32_t)(r * 128 + ldc * 16)),
                      src + (size_t)r * HDIM + ldc * 8);
        }
    };
    auto issueKV = [&](int kt, bool real) {
        if (real) {
            const uint32_t st = 16384u + (uint32_t)(kt & 3) * FSTG;
            const size_t off = (size_t)kt * 128 * HDIM;
            loadTile(st,           Kp + off);
            loadTile(st + 16384u,  Vp + off);
        }
        asm volatile("cp.async.commit_group;" ::: "memory");
    };

    loadTile(0u, Qp);
    issueKV(0, true);
    issueKV(1, 1 <= qt);
    issueKV(2, 2 <= qt);
    issueKV(3, 3 <= qt);

    float o[9][4];
    #pragma unroll
    for (int ng = 0; ng < 9; ng++)
        #pragma unroll
        for (int r = 0; r < 4; r++) o[ng][r] = 0.f;
    float m_[2] = {-INFINITY, -INFINITY};

    const int arow = lane & 15;
    const int akc  = (lane & 16) >> 1;
    const int brow = (lane & 7) | ((lane & 16) >> 1);
    const int bkc  = lane & 8;
    const int vrow = lane & 15;
    const int vsel = ((lane >> 4) & 1) * 16;

    const uint32_t ones2[2] = {0x3C003C00u, 0x3C003C00u};
    const float scale = 0.03125f;   // 1/sqrt(1024)

    for (int kt = 0; kt <= qt; kt++) {
        asm volatile("cp.async.wait_group 3;" ::: "memory");
        __syncthreads();

        const uint32_t st = sb + 16384u + (uint32_t)(kt & 3) * FSTG;
        const bool diag = (kt == qt);
        const int bmax = diag ? wid : 7;
        const int nmax = diag ? (wid * 2 + 1) : 15;
        const int k0 = kt * 128;

        float s[16][4];
        #pragma unroll
        for (int ni = 0; ni < 16; ni++)
            #pragma unroll
            for (int r = 0; r < 4; r++) s[ni][r] = 0.f;

        #pragma unroll
        for (int ks = 0; ks < 4; ks++) {
            uint32_t a[4];
            const uint32_t offA = swz((uint32_t)((wid * 16 + arow) * 128 + (ks * 16 + akc) * 2));
            ldmx4(a[0], a[1], a[2], a[3], sb + offA);
            #pragma unroll
            for (int bi = 0; bi < 8; bi++) {
                if (bi <= bmax) {
                    const uint32_t offB = swz((uint32_t)((bi * 16 + brow) * 128 + (ks * 16 + bkc) * 2));
                    uint32_t r0, r1, r2, r3;
                    ldmx4(r0, r1, r2, r3, st + offB);
                    uint32_t b0[2] = {r0, r1}, b1[2] = {r2, r3};
                    mma16816(s[bi*2],   a, b0);
                    mma16816(s[bi*2+1], a, b1);
                }
            }
        }

        uint32_t ph[16][2];
        #pragma unroll
        for (int h = 0; h < 2; h++) {
            const int qg = q0 + wid * 16 + g4 + h * 8;
            float mx = -INFINITY;
            #pragma unroll
            for (int ni = 0; ni < 16; ni++) {
                if (ni <= nmax) {
                    #pragma unroll
                    for (int e = 0; e < 2; e++) {
                        float v = s[ni][h * 2 + e] * scale;
                        if (diag && (k0 + ni * 8 + t4 * 2 + e) > qg) v += -100000.f;
                        s[ni][h * 2 + e] = v;
                        mx = fmaxf(mx, v);
                    }
                }
            }
            mx = fmaxf(mx, __shfl_xor_sync(0xffffffffu, mx, 1));
            mx = fmaxf(mx, __shfl_xor_sync(0xffffffffu, mx, 2));
            const float mnew = fmaxf(m_[h], mx);
            const float corr = __expf(m_[h] - mnew);
            const float lm = mnew * LOG2E;
            m_[h] = mnew;
            #pragma unroll
            for (int ni = 0; ni < 16; ni++) {
                if (ni <= nmax) {
                    const float t0 = fmaf(s[ni][h * 2 + 0], LOG2E, -lm);
                    const float t1 = fmaf(s[ni][h * 2 + 1], LOG2E, -lm);
                    ph[ni][h] = exp2_h2(t0, t1);
                }
            }
            #pragma unroll
            for (int ng = 0; ng < 9; ng++) {
                o[ng][h * 2 + 0] *= corr;
                o[ng][h * 2 + 1] *= corr;
            }
        }

        #pragma unroll
        for (int kc = 0; kc < 8; kc++) {
            if (kc <= bmax) {
                uint32_t pa[4];
                pa[0] = ph[kc*2  ][0];
                pa[1] = ph[kc*2  ][1];
                pa[2] = ph[kc*2+1][0];
                pa[3] = ph[kc*2+1][1];
                #pragma unroll
                for (int dp = 0; dp < 4; dp++) {
                    const uint32_t offV = swz((uint32_t)((kc * 16 + vrow) * 128 + dp * 32 + vsel));
                    uint32_t v0, v1, v2, v3;
                    ldmx4t(v0, v1, v2, v3, st + 16384u + offV);
                    uint32_t bv0[2] = {v0, v1}, bv1[2] = {v2, v3};
                    mma16816(o[dp*2],   pa, bv0);
                    mma16816(o[dp*2+1], pa, bv1);
                }
                mma16816(o[8], pa, ones2);
            }
        }
        __syncthreads();
        issueKV(kt + 4, kt + 4 <= qt);
    }

    #pragma unroll
    for (int h = 0; h < 2; h++) {
        const float inv = 1.f / o[8][h * 2];
        const int qg = q0 + wid * 16 + g4 + h * 8;
        const size_t base = ((size_t)(b * SEQ + qg)) * EMBED + head * HDIM;
        #pragma unroll
        for (int ng = 0; ng < 8; ng++) {
            const float x = o[ng][h * 2 + 0] * inv;
            const float y = o[ng][h * 2 + 1] * inv;
            *(uint32_t*)(oh + base + ng * 8 + t4 * 2) = pack_h2(x, y);
        }
    }
}

// ---------------------------------------------------------------------------
extern "C" void kernel_launch(void* const* d_in, const int* in_sizes, int n_in,
                              void* d_out, int out_size)
{
    const float* key   = (const float*)d_in[0];
    const float* query = (const float*)d_in[1];
    const float* value = (const float*)d_in[2];
    const float* Wk    = (const float*)d_in[3];
    const float* Wq    = (const float*)d_in[4];
    const float* Wv    = (const float*)d_in[5];
    const float* Wo    = (const float*)d_in[6];
    float* out = (float*)d_out;

    __half *xa, *xb, *xc, *w0, *w1, *w2, *w3, *q16, *k16, *v16;
    cudaGetSymbolAddress((void**)&xa, g_xa);
    cudaGetSymbolAddress((void**)&xb, g_xb);
    cudaGetSymbolAddress((void**)&xc, g_xc);
    cudaGetSymbolAddress((void**)&w0, g_w0);
    cudaGetSymbolAddress((void**)&w1, g_w1);
    cudaGetSymbolAddress((void**)&w2, g_w2);
    cudaGetSymbolAddress((void**)&w3, g_w3);
    cudaGetSymbolAddress((void**)&q16, g_q16);
    cudaGetSymbolAddress((void**)&k16, g_k16);
    cudaGetSymbolAddress((void**)&v16, g_v16);

    cudaFuncSetAttribute(gemm_tc<true>,  cudaFuncAttributeMaxDynamicSharedMemorySize, GSMEM);
    cudaFuncSetAttribute(gemm_tc<false>, cudaFuncAttributeMaxDynamicSharedMemorySize, GSMEM);
    cudaFuncSetAttribute(flash_tc,       cudaFuncAttributeMaxDynamicSharedMemorySize, FSMEM);

    // fused conversions: 2 launches
    cvt_acts<<<dim3((M_TOT*EMBED)/4096, 3), 256>>>(query, key, value, xa, xb, xc);
    cvt_wts <<<dim3((EMBED*EMBED)/4096, 4), 256>>>(Wq, Wk, Wv, Wo, w0, w1, w2, w3);

    // fused Q/K/V projections (proven 128x128 tile, z selects the triple)
    gemm_tc<true><<<dim3(M_TOT/128, EMBED/128, 3), 256, GSMEM>>>(
        xa, xb, xc, w0, w1, w2, nullptr, q16, k16, v16);

    // flash writes fp16 AO into xa (input of final GEMM)
    flash_tc<<<dim3(SEQ/128, BATCH*HEADS), 256, FSMEM>>>(q16, k16, v16, xa);

    gemm_tc<false><<<dim3(M_TOT/128, EMBED/128, 1), 256, GSMEM>>>(
        xa, xa, xa, w3, w3, w3, out, nullptr, nullptr, nullptr);
}

// round 8
// speedup vs baseline: 1.2606x; 1.2606x over previous
#include <cuda_runtime.h>
#include <cuda_fp16.h>
#include <math.h>
#include <stdint.h>

#define EMBED 1024
#define HEADS 16
#define HDIM  64
#define BATCH 2
#define SEQ   2048
#define M_TOT (BATCH*SEQ)   // 4096

// ---------------- scratch (device globals; allocation-free) ----------------
__device__ __align__(16) __half g_xa[M_TOT*EMBED];   // query act / AO
__device__ __align__(16) __half g_xb[M_TOT*EMBED];   // key act
__device__ __align__(16) __half g_xc[M_TOT*EMBED];   // value act
__device__ __align__(16) __half g_w0[EMBED*EMBED];   // Wq
__device__ __align__(16) __half g_w1[EMBED*EMBED];   // Wk
__device__ __align__(16) __half g_w2[EMBED*EMBED];   // Wv
__device__ __align__(16) __half g_w3[EMBED*EMBED];   // Wo
__device__ __align__(16) __half g_q16[BATCH*HEADS*SEQ*HDIM];
__device__ __align__(16) __half g_k16[BATCH*HEADS*SEQ*HDIM];
__device__ __align__(16) __half g_v16[BATCH*HEADS*SEQ*HDIM];

// ---------------------------------------------------------------------------
// fp32 -> fp16, fused across tensors: blockIdx.y selects tensor.
// ---------------------------------------------------------------------------
__global__ __launch_bounds__(256) void cvt_acts(const float* __restrict__ a,
                                                const float* __restrict__ b,
                                                const float* __restrict__ c,
                                                __half* __restrict__ ha,
                                                __half* __restrict__ hb,
                                                __half* __restrict__ hc)
{
    const float* x = (blockIdx.y == 0) ? a : (blockIdx.y == 1) ? b : c;
    __half* h      = (blockIdx.y == 0) ? ha : (blockIdx.y == 1) ? hb : hc;
    const float4* src = (const float4*)x + (size_t)blockIdx.x * 1024;
    uint2* dst = (uint2*)h + (size_t)blockIdx.x * 1024;
    const int tid = threadIdx.x;
    #pragma unroll
    for (int j = 0; j < 4; j++) {
        float4 v = src[j * 256 + tid];
        __half2 p = __floats2half2_rn(v.x, v.y);
        __half2 q = __floats2half2_rn(v.z, v.w);
        uint2 r;
        r.x = reinterpret_cast<uint32_t&>(p);
        r.y = reinterpret_cast<uint32_t&>(q);
        dst[j * 256 + tid] = r;
    }
}

__global__ __launch_bounds__(256) void cvt_wts(const float* __restrict__ a,
                                               const float* __restrict__ b,
                                               const float* __restrict__ c,
                                               const float* __restrict__ d,
                                               __half* __restrict__ ha,
                                               __half* __restrict__ hb,
                                               __half* __restrict__ hc,
                                               __half* __restrict__ hd)
{
    const float* x = (blockIdx.y == 0) ? a : (blockIdx.y == 1) ? b
                   : (blockIdx.y == 2) ? c : d;
    __half* h      = (blockIdx.y == 0) ? ha : (blockIdx.y == 1) ? hb
                   : (blockIdx.y == 2) ? hc : hd;
    const float4* src = (const float4*)x + (size_t)blockIdx.x * 1024;
    uint2* dst = (uint2*)h + (size_t)blockIdx.x * 1024;
    const int tid = threadIdx.x;
    #pragma unroll
    for (int j = 0; j < 4; j++) {
        float4 v = src[j * 256 + tid];
        __half2 p = __floats2half2_rn(v.x, v.y);
        __half2 q = __floats2half2_rn(v.z, v.w);
        uint2 r;
        r.x = reinterpret_cast<uint32_t&>(p);
        r.y = reinterpret_cast<uint32_t&>(q);
        dst[j * 256 + tid] = r;
    }
}

// ---------------------------------------------------------------------------
// warp-MMA helpers
// ---------------------------------------------------------------------------
__device__ __forceinline__ uint32_t s2u(const void* p) {
    uint32_t a;
    asm("{ .reg .u64 t; cvta.to.shared.u64 t, %1; cvt.u32.u64 %0, t; }" : "=r"(a) : "l"(p));
    return a;
}

__device__ __forceinline__ void ldmx4(uint32_t& r0, uint32_t& r1, uint32_t& r2, uint32_t& r3,
                                      uint32_t addr)
{
    asm volatile("ldmatrix.sync.aligned.m8n8.x4.shared.b16 {%0,%1,%2,%3}, [%4];"
                 : "=r"(r0), "=r"(r1), "=r"(r2), "=r"(r3) : "r"(addr));
}

__device__ __forceinline__ void ldmx4t(uint32_t& r0, uint32_t& r1, uint32_t& r2, uint32_t& r3,
                                       uint32_t addr)
{
    asm volatile("ldmatrix.sync.aligned.m8n8.x4.trans.shared.b16 {%0,%1,%2,%3}, [%4];"
                 : "=r"(r0), "=r"(r1), "=r"(r2), "=r"(r3) : "r"(addr));
}

__device__ __forceinline__ void mma16816(float* d, const uint32_t* a, const uint32_t* b)
{
    asm volatile("mma.sync.aligned.m16n8k16.row.col.f32.f16.f16.f32 "
                 "{%0,%1,%2,%3}, {%4,%5,%6,%7}, {%8,%9}, {%0,%1,%2,%3};"
                 : "+f"(d[0]), "+f"(d[1]), "+f"(d[2]), "+f"(d[3])
                 : "r"(a[0]), "r"(a[1]), "r"(a[2]), "r"(a[3]), "r"(b[0]), "r"(b[1]));
}

__device__ __forceinline__ void cpasync16(uint32_t saddr, const void* gaddr)
{
    asm volatile("cp.async.cg.shared.global [%0], [%1], 16;" :: "r"(saddr), "l"(gaddr));
}

__device__ __forceinline__ uint32_t swz(uint32_t off) { return off ^ ((off >> 3) & 0x70); }

__device__ __forceinline__ uint32_t pack_h2(float x, float y) {
    __half2 t = __floats2half2_rn(x, y);
    return reinterpret_cast<uint32_t&>(t);
}

// exp2 of two fp32 values via fp16x2 MUFU; returns packed half2 {lo=exp2(t0), hi=exp2(t1)}
__device__ __forceinline__ uint32_t exp2_h2(float t0, float t1) {
    uint32_t r;
    asm("{ .reg .b32 t; cvt.rn.f16x2.f32 t, %2, %1; ex2.approx.f16x2 %0, t; }"
        : "=r"(r) : "f"(t0), "f"(t1));
    return r;
}

// ---------------------------------------------------------------------------
// Tensor-core GEMM (proven shape): C[m][n] = sum_k X[m][k]*W[n][k]
// CTA tile 128x128, BK=64, 8 warps (2m x 4n, warptile 64x32), 4-stage pipeline.
// blockIdx.z selects (X, W, out). SPLIT: fp16 (B,H,S,D); else fp32 (B,S,E).
// ---------------------------------------------------------------------------
#define GSTG  32768u
#define GSMEM (4 * GSTG)

template<bool SPLIT>
__global__ __launch_bounds__(256, 1) void gemm_tc(
    const __half* __restrict__ xa, const __half* __restrict__ xb, const __half* __restrict__ xc,
    const __half* __restrict__ wa, const __half* __restrict__ wb, const __half* __restrict__ wc,
    float* __restrict__ out,
    __half* __restrict__ oa, __half* __restrict__ ob, __half* __restrict__ oc)
{
    const int z = blockIdx.z;
    const __half* x16 = (z == 0) ? xa : (z == 1) ? xb : xc;
    const __half* w16 = (z == 0) ? wa : (z == 1) ? wb : wc;
    __half* outh      = (z == 0) ? oa : (z == 1) ? ob : oc;

    extern __shared__ char smg[];
    const uint32_t sb = s2u(smg);
    const int tid  = threadIdx.x;
    const int wid  = tid >> 5, lane = tid & 31;
    const int wm   = wid & 1;
    const int wn   = wid >> 1;
    const int m0   = blockIdx.x * 128;
    const int n0   = blockIdx.y * 128;

    const int ldr = tid >> 3;
    const int ldc = tid & 7;

    auto issue = [&](int c, bool real) {
        if (real) {
            const uint32_t sst = sb + (uint32_t)(c & 3) * GSTG;
            const int kc0 = c * 64;
            const __half* gA = x16 + (size_t)m0 * EMBED + kc0;
            const __half* gB = w16 + (size_t)n0 * EMBED + kc0;
            #pragma unroll
            for (int it = 0; it < 4; it++) {
                const int r = ldr + it * 32;
                const uint32_t o = swz((uint32_t)(r * 128 + ldc * 16));
                const size_t g = (size_t)r * EMBED + ldc * 8;
                cpasync16(sst +          o, gA + g);
                cpasync16(sst + 16384u + o, gB + g);
            }
        }
        asm volatile("cp.async.commit_group;" ::: "memory");
    };

    float d[4][4][4];
    #pragma unroll
    for (int mi = 0; mi < 4; mi++)
        #pragma unroll
        for (int ni = 0; ni < 4; ni++)
            #pragma unroll
            for (int r = 0; r < 4; r++) d[mi][ni][r] = 0.f;

    issue(0, true); issue(1, true); issue(2, true); issue(3, true);

    const int arow = lane & 15;
    const int akc  = (lane & 16) >> 1;
    const int brow = (lane & 7) | ((lane & 16) >> 1);
    const int bkc  = lane & 8;

    const int NCHUNK = EMBED / 64;   // 16
    for (int c = 0; c < NCHUNK; c++) {
        asm volatile("cp.async.wait_group 3;" ::: "memory");
        __syncthreads();

        const uint32_t sst = sb + (uint32_t)(c & 3) * GSTG;
        const uint32_t bBase = sst + 16384u;

        #pragma unroll
        for (int ks = 0; ks < 4; ks++) {
            uint32_t a[4][4];
            #pragma unroll
            for (int mi = 0; mi < 4; mi++) {
                const int row = wm * 64 + mi * 16 + arow;
                const uint32_t off = swz((uint32_t)(row * 128 + (ks * 16 + akc) * 2));
                ldmx4(a[mi][0], a[mi][1], a[mi][2], a[mi][3], sst + off);
            }
            uint32_t b[4][2];
            #pragma unroll
            for (int bi = 0; bi < 2; bi++) {
                const int row = wn * 32 + bi * 16 + brow;
                const uint32_t off = swz((uint32_t)(row * 128 + (ks * 16 + bkc) * 2));
                uint32_t r0, r1, r2, r3;
                ldmx4(r0, r1, r2, r3, bBase + off);
                b[bi*2  ][0] = r0; b[bi*2  ][1] = r1;
                b[bi*2+1][0] = r2; b[bi*2+1][1] = r3;
            }
            #pragma unroll
            for (int mi = 0; mi < 4; mi++)
                #pragma unroll
                for (int ni = 0; ni < 4; ni++)
                    mma16816(d[mi][ni], a[mi], b[ni]);
        }
        __syncthreads();
        issue(c + 4, c + 4 < NCHUNK);
    }

    const int g4 = lane >> 2, t4 = lane & 3;
    #pragma unroll
    for (int mi = 0; mi < 4; mi++) {
        #pragma unroll
        for (int half = 0; half < 2; half++) {
            const int m = m0 + wm * 64 + mi * 16 + g4 + half * 8;
            const int bb = m >> 11, ssq = m & (SEQ - 1);
            #pragma unroll
            for (int ni = 0; ni < 4; ni++) {
                const int n = n0 + wn * 32 + ni * 8 + t4 * 2;
                const float vx = d[mi][ni][half * 2 + 0];
                const float vy = d[mi][ni][half * 2 + 1];
                if (SPLIT) {
                    const int h = n >> 6, dd = n & 63;
                    const size_t idx = (((size_t)(bb * HEADS + h)) * SEQ + ssq) * HDIM + dd;
                    *(uint32_t*)(outh + idx) = pack_h2(vx, vy);
                } else {
                    float2 v; v.x = vx; v.y = vy;
                    *(float2*)(out + (size_t)m * EMBED + n) = v;
                }
            }
        }
    }
}

// ---------------------------------------------------------------------------
// Flash attention on HMMA — round-5 core, register-lean upgrades:
//  * raw fp32 scores in s[]; scale folded into SCLOG2E
//  * exp via ex2.approx.f16x2 computed INSIDE the PV loop (no ph array)
//  * l via P x ones MMA (o[8])
//  * Q fragments hoisted into registers before kv loop
// CTA: 128 q-rows; 8 warps x 16 q-rows; 4-stage KV pipeline.
// ---------------------------------------------------------------------------
#define FSTG  32768u
#define FSMEM (16384 + 4 * FSTG)
#define SCLOG2E 0.04508422002474647f   // (1/32) * log2(e)
#define MASK_RAW -3200000.0f           // -100000 / (1/32)

__global__ __launch_bounds__(256, 1) void flash_tc(
    const __half* __restrict__ q16, const __half* __restrict__ k16,
    const __half* __restrict__ v16, __half* __restrict__ oh)
{
    extern __shared__ char smf[];
    const uint32_t sb = s2u(smf);
    const int tid  = threadIdx.x;
    const int wid  = tid >> 5, lane = tid & 31;
    const int g4   = lane >> 2, t4 = lane & 3;
    const int bh   = blockIdx.y;
    const int b    = bh >> 4, head = bh & 15;
    const int qt   = (int)gridDim.x - 1 - (int)blockIdx.x;   // heavy tiles first
    const int q0   = qt * 128;

    const size_t bo = (size_t)bh * SEQ * HDIM;
    const __half* Qp = q16 + bo + (size_t)q0 * HDIM;
    const __half* Kp = k16 + bo;
    const __half* Vp = v16 + bo;

    const int ldr = tid >> 3, ldc = tid & 7;
    auto loadTile = [&](uint32_t dst, const __half* src) {
        #pragma unroll
        for (int it = 0; it < 4; it++) {
            const int r = ldr + it * 32;
            cpasync16(sb + dst + swz((uint32_t)(r * 128 + ldc * 16)),
                      src + (size_t)r * HDIM + ldc * 8);
        }
    };
    auto issueKV = [&](int kt, bool real) {
        if (real) {
            const uint32_t st = 16384u + (uint32_t)(kt & 3) * FSTG;
            const size_t off = (size_t)kt * 128 * HDIM;
            loadTile(st,           Kp + off);
            loadTile(st + 16384u,  Vp + off);
        }
        asm volatile("cp.async.commit_group;" ::: "memory");
    };

    loadTile(0u, Qp);               // group 0 bundles Q + KV0
    issueKV(0, true);
    issueKV(1, 1 <= qt);
    issueKV(2, 2 <= qt);
    issueKV(3, 3 <= qt);

    const int arow = lane & 15;
    const int akc  = (lane & 16) >> 1;
    const int brow = (lane & 7) | ((lane & 16) >> 1);
    const int bkc  = lane & 8;
    const int vrow = lane & 15;
    const int vsel = ((lane >> 4) & 1) * 16;

    // wait for Q (+KV0) and hoist Q fragments into registers
    asm volatile("cp.async.wait_group 3;" ::: "memory");
    __syncthreads();
    uint32_t qf[4][4];
    #pragma unroll
    for (int ks = 0; ks < 4; ks++) {
        const uint32_t offA = swz((uint32_t)((wid * 16 + arow) * 128 + (ks * 16 + akc) * 2));
        ldmx4(qf[ks][0], qf[ks][1], qf[ks][2], qf[ks][3], sb + offA);
    }

    // o[0..7]: output accumulators; o[8]: row-sum (P x ones)
    float o[9][4];
    #pragma unroll
    for (int ng = 0; ng < 9; ng++)
        #pragma unroll
        for (int r = 0; r < 4; r++) o[ng][r] = 0.f;
    float m_[2] = {-INFINITY, -INFINITY};

    const uint32_t ones2[2] = {0x3C003C00u, 0x3C003C00u};

    for (int kt = 0; kt <= qt; kt++) {
        asm volatile("cp.async.wait_group 3;" ::: "memory");
        __syncthreads();

        const uint32_t st = sb + 16384u + (uint32_t)(kt & 3) * FSTG;
        const bool diag = (kt == qt);
        const int k0 = kt * 128;

        // ---------------- S = Q K^T (raw scores) ----------------
        float s[16][4];
        #pragma unroll
        for (int ni = 0; ni < 16; ni++)
            #pragma unroll
            for (int r = 0; r < 4; r++) s[ni][r] = 0.f;

        #pragma unroll
        for (int ks = 0; ks < 4; ks++) {
            #pragma unroll
            for (int bi = 0; bi < 8; bi++) {
                const uint32_t offB = swz((uint32_t)((bi * 16 + brow) * 128 + (ks * 16 + bkc) * 2));
                uint32_t r0, r1, r2, r3;
                ldmx4(r0, r1, r2, r3, st + offB);
                uint32_t b0[2] = {r0, r1}, b1[2] = {r2, r3};
                mma16816(s[bi*2],   qf[ks], b0);
                mma16816(s[bi*2+1], qf[ks], b1);
            }
        }

        // ---------------- mask + max bookkeeping (raw space) ----------------
        if (diag) {
            #pragma unroll
            for (int ni = 0; ni < 16; ni++) {
                const int kg = k0 + ni * 8 + t4 * 2;
                #pragma unroll
                for (int h = 0; h < 2; h++) {
                    const int qg = q0 + wid * 16 + g4 + h * 8;
                    if (kg     > qg) s[ni][h*2+0] += MASK_RAW;
                    if (kg + 1 > qg) s[ni][h*2+1] += MASK_RAW;
                }
            }
        }
        #pragma unroll
        for (int h = 0; h < 2; h++) {
            float mx = -INFINITY;
            #pragma unroll
            for (int ni = 0; ni < 16; ni++)
                mx = fmaxf(mx, fmaxf(s[ni][h*2+0], s[ni][h*2+1]));
            mx = fmaxf(mx, __shfl_xor_sync(0xffffffffu, mx, 1));
            mx = fmaxf(mx, __shfl_xor_sync(0xffffffffu, mx, 2));
            const float mnew = fmaxf(m_[h], mx);
            const float corr = exp2f((m_[h] - mnew) * SCLOG2E);
            m_[h] = mnew;
            #pragma unroll
            for (int ng = 0; ng < 9; ng++) {
                o[ng][h*2+0] *= corr;
                o[ng][h*2+1] *= corr;
            }
        }

        // ---------------- O += P V ; l += P x 1 (exp fused here) ------------
        const float lm0 = m_[0] * SCLOG2E;
        const float lm1 = m_[1] * SCLOG2E;
        #pragma unroll
        for (int kc = 0; kc < 8; kc++) {
            uint32_t pa[4];
            pa[0] = exp2_h2(fmaf(s[kc*2  ][0], SCLOG2E, -lm0),
                            fmaf(s[kc*2  ][1], SCLOG2E, -lm0));
            pa[1] = exp2_h2(fmaf(s[kc*2  ][2], SCLOG2E, -lm1),
                            fmaf(s[kc*2  ][3], SCLOG2E, -lm1));
            pa[2] = exp2_h2(fmaf(s[kc*2+1][0], SCLOG2E, -lm0),
                            fmaf(s[kc*2+1][1], SCLOG2E, -lm0));
            pa[3] = exp2_h2(fmaf(s[kc*2+1][2], SCLOG2E, -lm1),
                            fmaf(s[kc*2+1][3], SCLOG2E, -lm1));
            #pragma unroll
            for (int dp = 0; dp < 4; dp++) {
                const uint32_t offV = swz((uint32_t)((kc * 16 + vrow) * 128 + dp * 32 + vsel));
                uint32_t v0, v1, v2, v3;
                ldmx4t(v0, v1, v2, v3, st + 16384u + offV);
                uint32_t bv0[2] = {v0, v1}, bv1[2] = {v2, v3};
                mma16816(o[dp*2],   pa, bv0);
                mma16816(o[dp*2+1], pa, bv1);
            }
            mma16816(o[8], pa, ones2);
        }
        __syncthreads();
        issueKV(kt + 4, kt + 4 <= qt);
    }

    // ---------------- epilogue: O/l -> fp16 (B,S,E) ----------------
    #pragma unroll
    for (int h = 0; h < 2; h++) {
        const float inv = 1.f / o[8][h * 2];
        const int qg = q0 + wid * 16 + g4 + h * 8;
        const size_t base = ((size_t)(b * SEQ + qg)) * EMBED + head * HDIM;
        #pragma unroll
        for (int ng = 0; ng < 8; ng++) {
            const float x = o[ng][h * 2 + 0] * inv;
            const float y = o[ng][h * 2 + 1] * inv;
            *(uint32_t*)(oh + base + ng * 8 + t4 * 2) = pack_h2(x, y);
        }
    }
}

// ---------------------------------------------------------------------------
extern "C" void kernel_launch(void* const* d_in, const int* in_sizes, int n_in,
                              void* d_out, int out_size)
{
    const float* key   = (const float*)d_in[0];
    const float* query = (const float*)d_in[1];
    const float* value = (const float*)d_in[2];
    const float* Wk    = (const float*)d_in[3];
    const float* Wq    = (const float*)d_in[4];
    const float* Wv    = (const float*)d_in[5];
    const float* Wo    = (const float*)d_in[6];
    float* out = (float*)d_out;

    __half *xa, *xb, *xc, *w0, *w1, *w2, *w3, *q16, *k16, *v16;
    cudaGetSymbolAddress((void**)&xa, g_xa);
    cudaGetSymbolAddress((void**)&xb, g_xb);
    cudaGetSymbolAddress((void**)&xc, g_xc);
    cudaGetSymbolAddress((void**)&w0, g_w0);
    cudaGetSymbolAddress((void**)&w1, g_w1);
    cudaGetSymbolAddress((void**)&w2, g_w2);
    cudaGetSymbolAddress((void**)&w3, g_w3);
    cudaGetSymbolAddress((void**)&q16, g_q16);
    cudaGetSymbolAddress((void**)&k16, g_k16);
    cudaGetSymbolAddress((void**)&v16, g_v16);

    cudaFuncSetAttribute(gemm_tc<true>,  cudaFuncAttributeMaxDynamicSharedMemorySize, GSMEM);
    cudaFuncSetAttribute(gemm_tc<false>, cudaFuncAttributeMaxDynamicSharedMemorySize, GSMEM);
    cudaFuncSetAttribute(flash_tc,       cudaFuncAttributeMaxDynamicSharedMemorySize, FSMEM);

    cvt_acts<<<dim3((M_TOT*EMBED)/4096, 3), 256>>>(query, key, value, xa, xb, xc);
    cvt_wts <<<dim3((EMBED*EMBED)/4096, 4), 256>>>(Wq, Wk, Wv, Wo, w0, w1, w2, w3);

    gemm_tc<true><<<dim3(M_TOT/128, EMBED/128, 3), 256, GSMEM>>>(
        xa, xb, xc, w0, w1, w2, nullptr, q16, k16, v16);

    flash_tc<<<dim3(SEQ/128, BATCH*HEADS), 256, FSMEM>>>(q16, k16, v16, xa);

    gemm_tc<false><<<dim3(M_TOT/128, EMBED/128, 1), 256, GSMEM>>>(
        xa, xa, xa, w3, w3, w3, out, nullptr, nullptr, nullptr);
}

// round 9
// speedup vs baseline: 1.4193x; 1.1258x over previous
#include <cuda_runtime.h>
#include <cuda_fp16.h>
#include <math.h>
#include <stdint.h>

#define EMBED 1024
#define HEADS 16
#define HDIM  64
#define BATCH 2
#define SEQ   2048
#define M_TOT (BATCH*SEQ)   // 4096

// ---------------- scratch (device globals; allocation-free) ----------------
__device__ __align__(16) __half g_xa[M_TOT*EMBED];   // query act / AO
__device__ __align__(16) __half g_xb[M_TOT*EMBED];   // key act
__device__ __align__(16) __half g_xc[M_TOT*EMBED];   // value act
__device__ __align__(16) __half g_w0[EMBED*EMBED];   // Wq
__device__ __align__(16) __half g_w1[EMBED*EMBED];   // Wk
__device__ __align__(16) __half g_w2[EMBED*EMBED];   // Wv
__device__ __align__(16) __half g_w3[EMBED*EMBED];   // Wo
__device__ __align__(16) __half g_q16[BATCH*HEADS*SEQ*HDIM];
__device__ __align__(16) __half g_k16[BATCH*HEADS*SEQ*HDIM];
__device__ __align__(16) __half g_v16[BATCH*HEADS*SEQ*HDIM];

// ---------------------------------------------------------------------------
// fp32 -> fp16, ALL seven tensors in one launch. 4096 blocks x 4096 floats.
// blocks [0,3072): acts (1024 each); [3072,4096): weights (256 each).
// ---------------------------------------------------------------------------
__global__ __launch_bounds__(256) void cvt_all(
    const float* __restrict__ q,  const float* __restrict__ k,
    const float* __restrict__ v,
    const float* __restrict__ wq, const float* __restrict__ wk,
    const float* __restrict__ wv, const float* __restrict__ wo,
    __half* __restrict__ xa, __half* __restrict__ xb, __half* __restrict__ xc,
    __half* __restrict__ w0, __half* __restrict__ w1,
    __half* __restrict__ w2, __half* __restrict__ w3)
{
    const int blk = blockIdx.x;
    const float* x; __half* h; int off;
    if (blk < 1024)      { x = q;  h = xa; off = blk; }
    else if (blk < 2048) { x = k;  h = xb; off = blk - 1024; }
    else if (blk < 3072) { x = v;  h = xc; off = blk - 2048; }
    else if (blk < 3328) { x = wq; h = w0; off = blk - 3072; }
    else if (blk < 3584) { x = wk; h = w1; off = blk - 3328; }
    else if (blk < 3840) { x = wv; h = w2; off = blk - 3584; }
    else                 { x = wo; h = w3; off = blk - 3840; }

    const float4* src = (const float4*)x + (size_t)off * 1024;
    uint2* dst = (uint2*)h + (size_t)off * 1024;
    const int tid = threadIdx.x;
    #pragma unroll
    for (int j = 0; j < 4; j++) {
        float4 vv = src[j * 256 + tid];
        __half2 p = __floats2half2_rn(vv.x, vv.y);
        __half2 qq = __floats2half2_rn(vv.z, vv.w);
        uint2 r;
        r.x = reinterpret_cast<uint32_t&>(p);
        r.y = reinterpret_cast<uint32_t&>(qq);
        dst[j * 256 + tid] = r;
    }
}

// ---------------------------------------------------------------------------
// warp-MMA helpers
// ---------------------------------------------------------------------------
__device__ __forceinline__ uint32_t s2u(const void* p) {
    uint32_t a;
    asm("{ .reg .u64 t; cvta.to.shared.u64 t, %1; cvt.u32.u64 %0, t; }" : "=r"(a) : "l"(p));
    return a;
}

__device__ __forceinline__ void ldmx4(uint32_t& r0, uint32_t& r1, uint32_t& r2, uint32_t& r3,
                                      uint32_t addr)
{
    asm volatile("ldmatrix.sync.aligned.m8n8.x4.shared.b16 {%0,%1,%2,%3}, [%4];"
                 : "=r"(r0), "=r"(r1), "=r"(r2), "=r"(r3) : "r"(addr));
}

__device__ __forceinline__ void ldmx4t(uint32_t& r0, uint32_t& r1, uint32_t& r2, uint32_t& r3,
                                       uint32_t addr)
{
    asm volatile("ldmatrix.sync.aligned.m8n8.x4.trans.shared.b16 {%0,%1,%2,%3}, [%4];"
                 : "=r"(r0), "=r"(r1), "=r"(r2), "=r"(r3) : "r"(addr));
}

__device__ __forceinline__ void mma16816(float* d, const uint32_t* a, const uint32_t* b)
{
    asm volatile("mma.sync.aligned.m16n8k16.row.col.f32.f16.f16.f32 "
                 "{%0,%1,%2,%3}, {%4,%5,%6,%7}, {%8,%9}, {%0,%1,%2,%3};"
                 : "+f"(d[0]), "+f"(d[1]), "+f"(d[2]), "+f"(d[3])
                 : "r"(a[0]), "r"(a[1]), "r"(a[2]), "r"(a[3]), "r"(b[0]), "r"(b[1]));
}

__device__ __forceinline__ void cpasync16(uint32_t saddr, const void* gaddr)
{
    asm volatile("cp.async.cg.shared.global [%0], [%1], 16;" :: "r"(saddr), "l"(gaddr));
}

__device__ __forceinline__ uint32_t swz(uint32_t off) { return off ^ ((off >> 3) & 0x70); }

__device__ __forceinline__ uint32_t pack_h2(float x, float y) {
    __half2 t = __floats2half2_rn(x, y);
    return reinterpret_cast<uint32_t&>(t);
}

__device__ __forceinline__ uint32_t exp2_h2(float t0, float t1) {
    uint32_t r;
    asm("{ .reg .b32 t; cvt.rn.f16x2.f32 t, %2, %1; ex2.approx.f16x2 %0, t; }"
        : "=r"(r) : "f"(t0), "f"(t1));
    return r;
}

// ---------------------------------------------------------------------------
// Tensor-core GEMM: CTA tile 128x128, BK=64, 8 warps (2m x 4n), 2-stage
// pipeline, 2 CTAs/SM (__launch_bounds__(256,2) caps regs at 128).
// blockIdx.z selects (X, W, out). SPLIT: fp16 (B,H,S,D); else fp32 (B,S,E).
// ---------------------------------------------------------------------------
#define GSTG  32768u
#define GSMEM (2 * GSTG)   // 64 KB -> 2 CTAs/SM

template<bool SPLIT>
__global__ __launch_bounds__(256, 2) void gemm_tc(
    const __half* __restrict__ xa, const __half* __restrict__ xb, const __half* __restrict__ xc,
    const __half* __restrict__ wa, const __half* __restrict__ wb, const __half* __restrict__ wc,
    float* __restrict__ out,
    __half* __restrict__ oa, __half* __restrict__ ob, __half* __restrict__ oc)
{
    const int z = blockIdx.z;
    const __half* x16 = (z == 0) ? xa : (z == 1) ? xb : xc;
    const __half* w16 = (z == 0) ? wa : (z == 1) ? wb : wc;
    __half* outh      = (z == 0) ? oa : (z == 1) ? ob : oc;

    extern __shared__ char smg[];
    const uint32_t sb = s2u(smg);
    const int tid  = threadIdx.x;
    const int wid  = tid >> 5, lane = tid & 31;
    const int wm   = wid & 1;
    const int wn   = wid >> 1;
    const int m0   = blockIdx.x * 128;
    const int n0   = blockIdx.y * 128;

    const int ldr = tid >> 3;
    const int ldc = tid & 7;

    auto issue = [&](int c, bool real) {
        if (real) {
            const uint32_t sst = sb + (uint32_t)(c & 1) * GSTG;
            const int kc0 = c * 64;
            const __half* gA = x16 + (size_t)m0 * EMBED + kc0;
            const __half* gB = w16 + (size_t)n0 * EMBED + kc0;
            #pragma unroll
            for (int it = 0; it < 4; it++) {
                const int r = ldr + it * 32;
                const uint32_t o = swz((uint32_t)(r * 128 + ldc * 16));
                const size_t g = (size_t)r * EMBED + ldc * 8;
                cpasync16(sst +          o, gA + g);
                cpasync16(sst + 16384u + o, gB + g);
            }
        }
        asm volatile("cp.async.commit_group;" ::: "memory");
    };

    float d[4][4][4];
    #pragma unroll
    for (int mi = 0; mi < 4; mi++)
        #pragma unroll
        for (int ni = 0; ni < 4; ni++)
            #pragma unroll
            for (int r = 0; r < 4; r++) d[mi][ni][r] = 0.f;

    issue(0, true); issue(1, true);

    const int arow = lane & 15;
    const int akc  = (lane & 16) >> 1;
    const int brow = (lane & 7) | ((lane & 16) >> 1);
    const int bkc  = lane & 8;

    const int NCHUNK = EMBED / 64;   // 16
    for (int c = 0; c < NCHUNK; c++) {
        asm volatile("cp.async.wait_group 1;" ::: "memory");
        __syncthreads();

        const uint32_t sst = sb + (uint32_t)(c & 1) * GSTG;
        const uint32_t bBase = sst + 16384u;

        #pragma unroll
        for (int ks = 0; ks < 4; ks++) {
            uint32_t a[4][4];
            #pragma unroll
            for (int mi = 0; mi < 4; mi++) {
                const int row = wm * 64 + mi * 16 + arow;
                const uint32_t off = swz((uint32_t)(row * 128 + (ks * 16 + akc) * 2));
                ldmx4(a[mi][0], a[mi][1], a[mi][2], a[mi][3], sst + off);
            }
            uint32_t b[4][2];
            #pragma unroll
            for (int bi = 0; bi < 2; bi++) {
                const int row = wn * 32 + bi * 16 + brow;
                const uint32_t off = swz((uint32_t)(row * 128 + (ks * 16 + bkc) * 2));
                uint32_t r0, r1, r2, r3;
                ldmx4(r0, r1, r2, r3, bBase + off);
                b[bi*2  ][0] = r0; b[bi*2  ][1] = r1;
                b[bi*2+1][0] = r2; b[bi*2+1][1] = r3;
            }
            #pragma unroll
            for (int mi = 0; mi < 4; mi++)
                #pragma unroll
                for (int ni = 0; ni < 4; ni++)
                    mma16816(d[mi][ni], a[mi], b[ni]);
        }
        __syncthreads();
        issue(c + 2, c + 2 < NCHUNK);
    }

    const int g4 = lane >> 2, t4 = lane & 3;
    #pragma unroll
    for (int mi = 0; mi < 4; mi++) {
        #pragma unroll
        for (int half = 0; half < 2; half++) {
            const int m = m0 + wm * 64 + mi * 16 + g4 + half * 8;
            const int bb = m >> 11, ssq = m & (SEQ - 1);
            #pragma unroll
            for (int ni = 0; ni < 4; ni++) {
                const int n = n0 + wn * 32 + ni * 8 + t4 * 2;
                const float vx = d[mi][ni][half * 2 + 0];
                const float vy = d[mi][ni][half * 2 + 1];
                if (SPLIT) {
                    const int h = n >> 6, dd = n & 63;
                    const size_t idx = (((size_t)(bb * HEADS + h)) * SEQ + ssq) * HDIM + dd;
                    *(uint32_t*)(outh + idx) = pack_h2(vx, vy);
                } else {
                    float2 v; v.x = vx; v.y = vy;
                    *(float2*)(out + (size_t)m * EMBED + n) = v;
                }
            }
        }
    }
}

// ---------------------------------------------------------------------------
// Flash attention on HMMA (round-8 proven version, unchanged).
// ---------------------------------------------------------------------------
#define FSTG  32768u
#define FSMEM (16384 + 4 * FSTG)
#define SCLOG2E 0.04508422002474647f   // (1/32) * log2(e)
#define MASK_RAW -3200000.0f           // -100000 / (1/32)

__global__ __launch_bounds__(256, 1) void flash_tc(
    const __half* __restrict__ q16, const __half* __restrict__ k16,
    const __half* __restrict__ v16, __half* __restrict__ oh)
{
    extern __shared__ char smf[];
    const uint32_t sb = s2u(smf);
    const int tid  = threadIdx.x;
    const int wid  = tid >> 5, lane = tid & 31;
    const int g4   = lane >> 2, t4 = lane & 3;
    const int bh   = blockIdx.y;
    const int b    = bh >> 4, head = bh & 15;
    const int qt   = (int)gridDim.x - 1 - (int)blockIdx.x;
    const int q0   = qt * 128;

    const size_t bo = (size_t)bh * SEQ * HDIM;
    const __half* Qp = q16 + bo + (size_t)q0 * HDIM;
    const __half* Kp = k16 + bo;
    const __half* Vp = v16 + bo;

    const int ldr = tid >> 3, ldc = tid & 7;
    auto loadTile = [&](uint32_t dst, const __half* src) {
        #pragma unroll
        for (int it = 0; it < 4; it++) {
            const int r = ldr + it * 32;
            cpasync16(sb + dst + swz((uint32_t)(r * 128 + ldc * 16)),
                      src + (size_t)r * HDIM + ldc * 8);
        }
    };
    auto issueKV = [&](int kt, bool real) {
        if (real) {
            const uint32_t st = 16384u + (uint32_t)(kt & 3) * FSTG;
            const size_t off = (size_t)kt * 128 * HDIM;
            loadTile(st,           Kp + off);
            loadTile(st + 16384u,  Vp + off);
        }
        asm volatile("cp.async.commit_group;" ::: "memory");
    };

    loadTile(0u, Qp);
    issueKV(0, true);
    issueKV(1, 1 <= qt);
    issueKV(2, 2 <= qt);
    issueKV(3, 3 <= qt);

    const int arow = lane & 15;
    const int akc  = (lane & 16) >> 1;
    const int brow = (lane & 7) | ((lane & 16) >> 1);
    const int bkc  = lane & 8;
    const int vrow = lane & 15;
    const int vsel = ((lane >> 4) & 1) * 16;

    asm volatile("cp.async.wait_group 3;" ::: "memory");
    __syncthreads();
    uint32_t qf[4][4];
    #pragma unroll
    for (int ks = 0; ks < 4; ks++) {
        const uint32_t offA = swz((uint32_t)((wid * 16 + arow) * 128 + (ks * 16 + akc) * 2));
        ldmx4(qf[ks][0], qf[ks][1], qf[ks][2], qf[ks][3], sb + offA);
    }

    float o[9][4];
    #pragma unroll
    for (int ng = 0; ng < 9; ng++)
        #pragma unroll
        for (int r = 0; r < 4; r++) o[ng][r] = 0.f;
    float m_[2] = {-INFINITY, -INFINITY};

    const uint32_t ones2[2] = {0x3C003C00u, 0x3C003C00u};

    for (int kt = 0; kt <= qt; kt++) {
        asm volatile("cp.async.wait_group 3;" ::: "memory");
        __syncthreads();

        const uint32_t st = sb + 16384u + (uint32_t)(kt & 3) * FSTG;
        const bool diag = (kt == qt);
        const int k0 = kt * 128;

        float s[16][4];
        #pragma unroll
        for (int ni = 0; ni < 16; ni++)
            #pragma unroll
            for (int r = 0; r < 4; r++) s[ni][r] = 0.f;

        #pragma unroll
        for (int ks = 0; ks < 4; ks++) {
            #pragma unroll
            for (int bi = 0; bi < 8; bi++) {
                const uint32_t offB = swz((uint32_t)((bi * 16 + brow) * 128 + (ks * 16 + bkc) * 2));
                uint32_t r0, r1, r2, r3;
                ldmx4(r0, r1, r2, r3, st + offB);
                uint32_t b0[2] = {r0, r1}, b1[2] = {r2, r3};
                mma16816(s[bi*2],   qf[ks], b0);
                mma16816(s[bi*2+1], qf[ks], b1);
            }
        }

        if (diag) {
            #pragma unroll
            for (int ni = 0; ni < 16; ni++) {
                const int kg = k0 + ni * 8 + t4 * 2;
                #pragma unroll
                for (int h = 0; h < 2; h++) {
                    const int qg = q0 + wid * 16 + g4 + h * 8;
                    if (kg     > qg) s[ni][h*2+0] += MASK_RAW;
                    if (kg + 1 > qg) s[ni][h*2+1] += MASK_RAW;
                }
            }
        }
        #pragma unroll
        for (int h = 0; h < 2; h++) {
            float mx = -INFINITY;
            #pragma unroll
            for (int ni = 0; ni < 16; ni++)
                mx = fmaxf(mx, fmaxf(s[ni][h*2+0], s[ni][h*2+1]));
            mx = fmaxf(mx, __shfl_xor_sync(0xffffffffu, mx, 1));
            mx = fmaxf(mx, __shfl_xor_sync(0xffffffffu, mx, 2));
            const float mnew = fmaxf(m_[h], mx);
            const float corr = exp2f((m_[h] - mnew) * SCLOG2E);
            m_[h] = mnew;
            #pragma unroll
            for (int ng = 0; ng < 9; ng++) {
                o[ng][h*2+0] *= corr;
                o[ng][h*2+1] *= corr;
            }
        }

        const float lm0 = m_[0] * SCLOG2E;
        const float lm1 = m_[1] * SCLOG2E;
        #pragma unroll
        for (int kc = 0; kc < 8; kc++) {
            uint32_t pa[4];
            pa[0] = exp2_h2(fmaf(s[kc*2  ][0], SCLOG2E, -lm0),
                            fmaf(s[kc*2  ][1], SCLOG2E, -lm0));
            pa[1] = exp2_h2(fmaf(s[kc*2  ][2], SCLOG2E, -lm1),
                            fmaf(s[kc*2  ][3], SCLOG2E, -lm1));
            pa[2] = exp2_h2(fmaf(s[kc*2+1][0], SCLOG2E, -lm0),
                            fmaf(s[kc*2+1][1], SCLOG2E, -lm0));
            pa[3] = exp2_h2(fmaf(s[kc*2+1][2], SCLOG2E, -lm1),
                            fmaf(s[kc*2+1][3], SCLOG2E, -lm1));
            #pragma unroll
            for (int dp = 0; dp < 4; dp++) {
                const uint32_t offV = swz((uint32_t)((kc * 16 + vrow) * 128 + dp * 32 + vsel));
                uint32_t v0, v1, v2, v3;
                ldmx4t(v0, v1, v2, v3, st + 16384u + offV);
                uint32_t bv0[2] = {v0, v1}, bv1[2] = {v2, v3};
                mma16816(o[dp*2],   pa, bv0);
                mma16816(o[dp*2+1], pa, bv1);
            }
            mma16816(o[8], pa, ones2);
        }
        __syncthreads();
        issueKV(kt + 4, kt + 4 <= qt);
    }

    #pragma unroll
    for (int h = 0; h < 2; h++) {
        const float inv = 1.f / o[8][h * 2];
        const int qg = q0 + wid * 16 + g4 + h * 8;
        const size_t base = ((size_t)(b * SEQ + qg)) * EMBED + head * HDIM;
        #pragma unroll
        for (int ng = 0; ng < 8; ng++) {
            const float x = o[ng][h * 2 + 0] * inv;
            const float y = o[ng][h * 2 + 1] * inv;
            *(uint32_t*)(oh + base + ng * 8 + t4 * 2) = pack_h2(x, y);
        }
    }
}

// ---------------------------------------------------------------------------
extern "C" void kernel_launch(void* const* d_in, const int* in_sizes, int n_in,
                              void* d_out, int out_size)
{
    const float* key   = (const float*)d_in[0];
    const float* query = (const float*)d_in[1];
    const float* value = (const float*)d_in[2];
    const float* Wk    = (const float*)d_in[3];
    const float* Wq    = (const float*)d_in[4];
    const float* Wv    = (const float*)d_in[5];
    const float* Wo    = (const float*)d_in[6];
    float* out = (float*)d_out;

    __half *xa, *xb, *xc, *w0, *w1, *w2, *w3, *q16, *k16, *v16;
    cudaGetSymbolAddress((void**)&xa, g_xa);
    cudaGetSymbolAddress((void**)&xb, g_xb);
    cudaGetSymbolAddress((void**)&xc, g_xc);
    cudaGetSymbolAddress((void**)&w0, g_w0);
    cudaGetSymbolAddress((void**)&w1, g_w1);
    cudaGetSymbolAddress((void**)&w2, g_w2);
    cudaGetSymbolAddress((void**)&w3, g_w3);
    cudaGetSymbolAddress((void**)&q16, g_q16);
    cudaGetSymbolAddress((void**)&k16, g_k16);
    cudaGetSymbolAddress((void**)&v16, g_v16);

    cudaFuncSetAttribute(gemm_tc<true>,  cudaFuncAttributeMaxDynamicSharedMemorySize, GSMEM);
    cudaFuncSetAttribute(gemm_tc<false>, cudaFuncAttributeMaxDynamicSharedMemorySize, GSMEM);
    cudaFuncSetAttribute(flash_tc,       cudaFuncAttributeMaxDynamicSharedMemorySize, FSMEM);

    cvt_all<<<4096, 256>>>(query, key, value, Wq, Wk, Wv, Wo,
                           xa, xb, xc, w0, w1, w2, w3);

    gemm_tc<true><<<dim3(M_TOT/128, EMBED/128, 3), 256, GSMEM>>>(
        xa, xb, xc, w0, w1, w2, nullptr, q16, k16, v16);

    flash_tc<<<dim3(SEQ/128, BATCH*HEADS), 256, FSMEM>>>(q16, k16, v16, xa);

    gemm_tc<false><<<dim3(M_TOT/128, EMBED/128, 1), 256, GSMEM>>>(
        xa, xa, xa, w3, w3, w3, out, nullptr, nullptr, nullptr);
}